// round 15
// baseline (speedup 1.0000x reference)
#include <cuda_runtime.h>
#include <math.h>

#define NMAX 50000
#define EMAX 800000
#define SB   512     // scan block size

typedef unsigned long long ull;

// ---------------- scratch (device globals; no allocation allowed) ------------
__device__ float d_h1[NMAX * 256];   // layer1 transformed features
__device__ float d_al1[NMAX * 4];
__device__ float d_ar1[NMAX * 4];
__device__ float d_g1[NMAX];
__device__ float d_x2[NMAX * 256];   // elu(normalized aggregate) = GEMM2 input
__device__ float d_h2[NMAX * 64];
__device__ float d_al2[NMAX];
__device__ float d_ar2[NMAX];
__device__ float d_g2[NMAX];
// CSR (edges sorted by destination)
__device__ int   d_deg[NMAX];
__device__ int   d_cur[NMAX];
__device__ int   d_rs[NMAX + 1];
__device__ int   d_bt[(NMAX + SB - 1) / SB];
__device__ int   d_srcs[EMAX];

__device__ __forceinline__ float elu_f(float v) {
    return v > 0.f ? v : (__expf(v) - 1.0f);
}

// packed fp32x2 FMA (sm_103a FFMA2 — only reachable via PTX)
__device__ __forceinline__ ull ffma2(ull a, ull b, ull c) {
    ull d;
    asm("fma.rn.f32x2 %0, %1, %2, %3;" : "=l"(d) : "l"(a), "l"(b), "l"(c));
    return d;
}

// ---------------- fp32x2 packed SGEMM, dup-B smem, double-buffered ------------
// C[N,M] = A[N,K] @ B[K,M]; 128xBN block tile, BK=16, 256 threads,
// 8x(4*JW) microtile (JW = BN/64). As K-transposed -> a-pairs are LDS.64
// broadcast. Bs stores every value DUPLICATED so b-pairs load directly as
// ulonglong2 (no mov.b64 packing in the hot loop): per k-step per thread,
// 4 LDS.64 + 2*JW LDS.128 + 16*JW FFMA2 and nothing else.
// Epilogue: 64-col groups align with heads; per-head att dots via 16-lane shfl.
template <int HS, int BN>
__global__ __launch_bounds__(256) void sgemm128(
        const float* __restrict__ A, const float* __restrict__ B,
        float* __restrict__ C, int N, int K, int M,
        const float* __restrict__ attl, const float* __restrict__ attr,
        float* __restrict__ alout, float* __restrict__ arout) {
    constexpr int JW = BN / 64;
    extern __shared__ float smf[];
    float* Asf = smf;                       // [2][16][132]
    float* Bsf = smf + 2 * 16 * 132;        // [2][16][2*BN] (duplicated pairs)
    const int ASTRIDE = 16 * 132;
    const int BSTRIDE = 16 * 2 * BN;

    int tid = threadIdx.x;
    int tx = tid & 15, ty = tid >> 4;
    int row0 = blockIdx.y * 128, col0 = blockIdx.x * BN;
    const int br = tid >> 4, bc = (tid & 15) * 4;

    ull acc[4][JW][4];
    #pragma unroll
    for (int p = 0; p < 4; p++)
        #pragma unroll
        for (int jw = 0; jw < JW; jw++)
            #pragma unroll
            for (int j = 0; j < 4; j++)
                acc[p][jw][j] = 0ull;

    float4 aR[2], bR[JW];
    // load tile 0
    #pragma unroll
    for (int i = 0; i < 2; i++) {
        int f = tid + i * 256;
        int r = f >> 2, c = (f & 3) * 4;
        int row = row0 + r;
        aR[i] = make_float4(0.f, 0.f, 0.f, 0.f);
        if (row < N) aR[i] = *(const float4*)&A[(size_t)row * K + c];
    }
    #pragma unroll
    for (int jw = 0; jw < JW; jw++)
        bR[jw] = *(const float4*)&B[(size_t)br * M + col0 + jw * 64 + bc];
    // store tile 0 to buf 0
    #pragma unroll
    for (int i = 0; i < 2; i++) {
        int f = tid + i * 256;
        int r = f >> 2, c = (f & 3) * 4;
        Asf[(c + 0) * 132 + r] = aR[i].x;
        Asf[(c + 1) * 132 + r] = aR[i].y;
        Asf[(c + 2) * 132 + r] = aR[i].z;
        Asf[(c + 3) * 132 + r] = aR[i].w;
    }
    #pragma unroll
    for (int jw = 0; jw < JW; jw++) {
        float* bp = &Bsf[br * 2 * BN + jw * 128 + bc * 2];
        *(float4*)&bp[0] = make_float4(bR[jw].x, bR[jw].x, bR[jw].y, bR[jw].y);
        *(float4*)&bp[4] = make_float4(bR[jw].z, bR[jw].z, bR[jw].w, bR[jw].w);
    }
    __syncthreads();

    int nt = K >> 4;
    for (int t = 0; t < nt; t++) {
        int abase = (t & 1) * ASTRIDE;
        int bbase = (t & 1) * BSTRIDE;
        // prefetch tile t+1 into regs
        if (t + 1 < nt) {
            int k0 = (t + 1) << 4;
            #pragma unroll
            for (int i = 0; i < 2; i++) {
                int f = tid + i * 256;
                int r = f >> 2, c = (f & 3) * 4;
                int row = row0 + r;
                aR[i] = make_float4(0.f, 0.f, 0.f, 0.f);
                if (row < N) aR[i] = *(const float4*)&A[(size_t)row * K + k0 + c];
            }
            #pragma unroll
            for (int jw = 0; jw < JW; jw++)
                bR[jw] = *(const float4*)&B[(size_t)(k0 + br) * M + col0 + jw * 64 + bc];
        }
        // compute 16 k-steps
        #pragma unroll
        for (int k = 0; k < 16; k++) {
            ull a[4];
            #pragma unroll
            for (int p = 0; p < 4; p++)
                a[p] = *(const ull*)&Asf[abase + k * 132 + ty * 8 + p * 2];
            #pragma unroll
            for (int jw = 0; jw < JW; jw++) {
                const ulonglong2* bp =
                    (const ulonglong2*)&Bsf[bbase + k * 2 * BN + jw * 128 + tx * 8];
                ulonglong2 b01 = bp[0];
                ulonglong2 b23 = bp[1];
                #pragma unroll
                for (int p = 0; p < 4; p++) {
                    acc[p][jw][0] = ffma2(a[p], b01.x, acc[p][jw][0]);
                    acc[p][jw][1] = ffma2(a[p], b01.y, acc[p][jw][1]);
                    acc[p][jw][2] = ffma2(a[p], b23.x, acc[p][jw][2]);
                    acc[p][jw][3] = ffma2(a[p], b23.y, acc[p][jw][3]);
                }
            }
        }
        // store prefetched tile to the other buffer
        if (t + 1 < nt) {
            int a2 = (abase ^ ASTRIDE);
            int b2 = (bbase ^ BSTRIDE);
            #pragma unroll
            for (int i = 0; i < 2; i++) {
                int f = tid + i * 256;
                int r = f >> 2, c = (f & 3) * 4;
                Asf[a2 + (c + 0) * 132 + r] = aR[i].x;
                Asf[a2 + (c + 1) * 132 + r] = aR[i].y;
                Asf[a2 + (c + 2) * 132 + r] = aR[i].z;
                Asf[a2 + (c + 3) * 132 + r] = aR[i].w;
            }
            #pragma unroll
            for (int jw = 0; jw < JW; jw++) {
                float* bp = &Bsf[b2 + br * 2 * BN + jw * 128 + bc * 2];
                *(float4*)&bp[0] = make_float4(bR[jw].x, bR[jw].x, bR[jw].y, bR[jw].y);
                *(float4*)&bp[4] = make_float4(bR[jw].z, bR[jw].z, bR[jw].w, bR[jw].w);
            }
            __syncthreads();
        }
    }
    // unpack accumulators: rows i = ty*8 + p*2 + {0,1}
    float accf[8][JW][4];
    #pragma unroll
    for (int p = 0; p < 4; p++)
        #pragma unroll
        for (int jw = 0; jw < JW; jw++)
            #pragma unroll
            for (int j = 0; j < 4; j++) {
                float2 f = *(float2*)&acc[p][jw][j];
                accf[p * 2 + 0][jw][j] = f.x;
                accf[p * 2 + 1][jw][j] = f.y;
            }
    #pragma unroll
    for (int i = 0; i < 8; i++) {
        int row = row0 + ty * 8 + i;
        if (row < N) {
            #pragma unroll
            for (int jw = 0; jw < JW; jw++)
                *(float4*)&C[(size_t)row * M + col0 + jw * 64 + tx * 4] =
                    make_float4(accf[i][jw][0], accf[i][jw][1],
                                accf[i][jw][2], accf[i][jw][3]);
        }
    }
    // fused attention-dot epilogue (per 64-col head group)
    #pragma unroll
    for (int jw = 0; jw < JW; jw++) {
        float lv[4], rv[4];
        #pragma unroll
        for (int j = 0; j < 4; j++) {
            lv[j] = attl[col0 + jw * 64 + tx * 4 + j];
            rv[j] = attr[col0 + jw * 64 + tx * 4 + j];
        }
        float pal[8], par[8];
        #pragma unroll
        for (int i = 0; i < 8; i++) {
            float sl = 0.f, sr = 0.f;
            #pragma unroll
            for (int j = 0; j < 4; j++) {
                sl += accf[i][jw][j] * lv[j];
                sr += accf[i][jw][j] * rv[j];
            }
            pal[i] = sl; par[i] = sr;
        }
        #pragma unroll
        for (int off = 1; off < 16; off <<= 1) {
            #pragma unroll
            for (int i = 0; i < 8; i++) {
                pal[i] += __shfl_xor_sync(0xffffffffu, pal[i], off);
                par[i] += __shfl_xor_sync(0xffffffffu, par[i], off);
            }
        }
        if (tx == 0) {
            int h = (col0 >> 6) + jw;
            #pragma unroll
            for (int i = 0; i < 8; i++) {
                int row = row0 + ty * 8 + i;
                if (row < N) {
                    alout[row * HS + h] = pal[i];
                    arout[row * HS + h] = par[i];
                }
            }
        }
    }
}

// ---------------- CSR build ---------------------------------------------------
__global__ void k_count(const int* __restrict__ dst, int E) {
    int e = blockIdx.x * blockDim.x + threadIdx.x;
    if (e < E) atomicAdd(&d_deg[dst[e]], 1);
}
// scan1 + layer1 guidance fused (same N-sized grid)
__global__ void k_scan1(const float* __restrict__ x, int N) {
    __shared__ int sm[SB];
    int i = blockIdx.x * SB + threadIdx.x;
    int v = (i < N) ? d_deg[i] : 0;
    sm[threadIdx.x] = v;
    if (i < N)
        d_g1[i] = -0.1f * logf(fabsf(x[(size_t)i * 128 + 127]) + 1e-6f);
    __syncthreads();
    #pragma unroll
    for (int off = 1; off < SB; off <<= 1) {
        int t = (threadIdx.x >= off) ? sm[threadIdx.x - off] : 0;
        __syncthreads();
        sm[threadIdx.x] += t;
        __syncthreads();
    }
    if (i < N) d_rs[i] = sm[threadIdx.x] - v;
    if (threadIdx.x == SB - 1) d_bt[blockIdx.x] = sm[SB - 1];
}
// scan2+scan3 merged: each block reduces d_bt[0..blockIdx) itself
__global__ void k_scan23(int N, int E) {
    __shared__ int soff;
    if (threadIdx.x == 0) soff = 0;
    __syncthreads();
    int v = (threadIdx.x < blockIdx.x) ? d_bt[threadIdx.x] : 0;
    #pragma unroll
    for (int off = 16; off; off >>= 1)
        v += __shfl_xor_sync(0xffffffffu, v, off);
    if ((threadIdx.x & 31) == 0 && v) atomicAdd(&soff, v);
    __syncthreads();
    int i = blockIdx.x * SB + threadIdx.x;
    if (i < N) d_rs[i] += soff;
    if (i == 0) d_rs[N] = E;
}
__global__ void k_scatter(const int* __restrict__ src, const int* __restrict__ dst, int E) {
    int e = blockIdx.x * blockDim.x + threadIdx.x;
    if (e >= E) return;
    int d = dst[e];
    int pos = d_rs[d] + atomicAdd(&d_cur[d], 1);
    d_srcs[pos] = src[e];
}

// ---------------- layer1 CSR aggregation: warp per dst node -------------------
__global__ void agg1_csr(int N) {
    int n = (blockIdx.x * blockDim.x + threadIdx.x) >> 5;
    int lane = threadIdx.x & 31;
    if (n >= N) return;
    int beg = d_rs[n], end = d_rs[n + 1];
    float alh = (lane < 4) ? d_al1[n * 4 + lane] : 0.f;
    float4 accA = make_float4(0.f, 0.f, 0.f, 0.f);
    float4 accB = make_float4(0.f, 0.f, 0.f, 0.f);
    float wsum = 0.f;
    for (int p = beg; p < end; p++) {
        int s = d_srcs[p];
        float ex = 0.f;
        if (lane < 4) {
            float v = alh + d_ar1[s * 4 + lane];
            v = v > 0.f ? v : 0.01f * v;        // leaky relu
            v += d_g1[s];                       // guidance (shift-safe softmax)
            ex = __expf(v);
            wsum += ex;
        }
        float w0 = __shfl_sync(0xffffffffu, ex, 0);
        float w1 = __shfl_sync(0xffffffffu, ex, 1);
        float w2 = __shfl_sync(0xffffffffu, ex, 2);
        float w3 = __shfl_sync(0xffffffffu, ex, 3);
        float wa = (lane < 16) ? w0 : w1;
        float wb = (lane < 16) ? w2 : w3;
        const float4* hs = (const float4*)&d_h1[(size_t)s * 256];
        float4 a = hs[lane];
        float4 b = hs[lane + 32];
        accA.x += a.x * wa; accA.y += a.y * wa; accA.z += a.z * wa; accA.w += a.w * wa;
        accB.x += b.x * wb; accB.y += b.y * wb; accB.z += b.z * wb; accB.w += b.w * wb;
    }
    float s0 = __shfl_sync(0xffffffffu, wsum, 0);
    float s1 = __shfl_sync(0xffffffffu, wsum, 1);
    float s2 = __shfl_sync(0xffffffffu, wsum, 2);
    float s3 = __shfl_sync(0xffffffffu, wsum, 3);
    float inva = 1.f / (((lane < 16) ? s0 : s1) + 1e-16f);
    float invb = 1.f / (((lane < 16) ? s2 : s3) + 1e-16f);
    accA.x = elu_f(accA.x * inva); accA.y = elu_f(accA.y * inva);
    accA.z = elu_f(accA.z * inva); accA.w = elu_f(accA.w * inva);
    accB.x = elu_f(accB.x * invb); accB.y = elu_f(accB.y * invb);
    accB.z = elu_f(accB.z * invb); accB.w = elu_f(accB.w * invb);
    float* xr = &d_x2[(size_t)n * 256];
    *(float4*)&xr[lane * 4] = accA;
    *(float4*)&xr[128 + lane * 4] = accB;
    if (lane == 31)
        d_g2[n] = -0.1f * logf(fabsf(accB.w) + 1e-6f);
}

// ---------------- layer2 CSR aggregation + normalize + ELU + final FC ---------
__global__ void agg2_csr(const float* __restrict__ fcw, const float* __restrict__ fcb,
                         float* __restrict__ out, int N) {
    int n = (blockIdx.x * blockDim.x + threadIdx.x) >> 5;
    int lane = threadIdx.x & 31;
    if (n >= N) return;
    int beg = d_rs[n], end = d_rs[n + 1];
    float aln = d_al2[n];
    float2 acc = make_float2(0.f, 0.f);
    float wsum = 0.f;
    for (int p = beg; p < end; p++) {
        int s = d_srcs[p];
        float ex = 0.f;
        if (lane == 0) {
            float v = aln + d_ar2[s];
            v = v > 0.f ? v : 0.01f * v;
            v += d_g2[s];
            ex = __expf(v);
            wsum += ex;
        }
        ex = __shfl_sync(0xffffffffu, ex, 0);
        float2 hv = ((const float2*)&d_h2[(size_t)s * 64])[lane];
        acc.x += hv.x * ex;
        acc.y += hv.y * ex;
    }
    wsum = __shfl_sync(0xffffffffu, wsum, 0);
    float inv = 1.f / (wsum + 1e-16f);
    float v0 = elu_f(acc.x * inv);
    float v1 = elu_f(acc.y * inv);
    float dot = v0 * fcw[2 * lane] + v1 * fcw[2 * lane + 1];
    #pragma unroll
    for (int off = 16; off; off >>= 1)
        dot += __shfl_xor_sync(0xffffffffu, dot, off);
    if (lane == 0) out[n] = dot + fcb[0];
}

// ---------------- host launcher ----------------------------------------------
extern "C" void kernel_launch(void* const* d_in, const int* in_sizes, int n_in,
                              void* d_out, int out_size) {
    const float* x     = (const float*)d_in[0];
    const int*   ei    = (const int*)d_in[1];
    const float* W1    = (const float*)d_in[2];
    const float* attl1 = (const float*)d_in[3];
    const float* attr1 = (const float*)d_in[4];
    const float* W2    = (const float*)d_in[5];
    const float* attl2 = (const float*)d_in[6];
    const float* attr2 = (const float*)d_in[7];
    const float* fcw   = (const float*)d_in[8];
    const float* fcb   = (const float*)d_in[9];
    float* out = (float*)d_out;

    int N = in_sizes[0] / 128;
    int E = in_sizes[1] / 2;
    const int* src = ei;
    const int* dst = ei + E;

    void *ph1, *ph2, *px2, *pdeg, *pcur;
    void *pal1, *par1, *pal2, *par2;
    cudaGetSymbolAddress(&ph1, d_h1);
    cudaGetSymbolAddress(&ph2, d_h2);
    cudaGetSymbolAddress(&px2, d_x2);
    cudaGetSymbolAddress(&pdeg, d_deg);
    cudaGetSymbolAddress(&pcur, d_cur);
    cudaGetSymbolAddress(&pal1, d_al1);
    cudaGetSymbolAddress(&par1, d_ar1);
    cudaGetSymbolAddress(&pal2, d_al2);
    cudaGetSymbolAddress(&par2, d_ar2);

    // one-time setup (first call is the uncaptured correctness run)
    static cudaStream_t s2 = nullptr;
    static cudaEvent_t evFork = nullptr, evJoin = nullptr;
    if (!s2) {
        cudaStreamCreateWithFlags(&s2, cudaStreamNonBlocking);
        cudaEventCreateWithFlags(&evFork, cudaEventDisableTiming);
        cudaEventCreateWithFlags(&evJoin, cudaEventDisableTiming);
        cudaFuncSetAttribute(sgemm128<4, 128>,
                             cudaFuncAttributeMaxDynamicSharedMemorySize, 50176);
    }

    const size_t smemA = 2 * 16 * 132 * sizeof(float);
    const size_t smem1 = smemA + 2 * 16 * 256 * sizeof(float);   // 49664 B
    const size_t smem2 = smemA + 2 * 16 * 128 * sizeof(float);   // 33280 B

    const int TB = 256;
    int gy = (N + 127) / 128;
    int nb = (N + SB - 1) / SB;

    // ---- fork: CSR build on s2, GEMM1 on main stream, concurrently ----
    cudaEventRecord(evFork, 0);
    cudaStreamWaitEvent(s2, evFork, 0);

    cudaMemsetAsync(pdeg, 0, sizeof(int) * (size_t)N, s2);             // 0
    cudaMemsetAsync(pcur, 0, sizeof(int) * (size_t)N, s2);             // 1
    k_count<<<(E + TB - 1) / TB, TB, 0, s2>>>(dst, E);                 // 2
    k_scan1<<<nb, SB, 0, s2>>>(x, N);                                  // 3 (+g1)
    k_scan23<<<nb, SB, 0, s2>>>(N, E);                                 // 4

    // M=256 with BN=128 block tile -> grid.x = 2 (round-14 bug: was 1)
    sgemm128<4, 128><<<dim3(2, gy), TB, smem1>>>(                      // 5 (main)
        x, W1, (float*)ph1, N, 128, 256,
        attl1, attr1, (float*)pal1, (float*)par1);

    k_scatter<<<(E + TB - 1) / TB, TB, 0, s2>>>(src, dst, E);          // 6
    cudaEventRecord(evJoin, s2);

    // ---- join: rest of the pipeline on the main stream ----
    cudaStreamWaitEvent(0, evJoin, 0);
    agg1_csr<<<(N * 32 + TB - 1) / TB, TB>>>(N);                       // 7
    sgemm128<1, 64><<<dim3(1, gy), TB, smem2>>>(                       // 8
        (const float*)px2, W2, (float*)ph2, N, 256, 64,
        attl2, attr2, (float*)pal2, (float*)par2);
    agg2_csr<<<(N * 32 + TB - 1) / TB, TB>>>(fcw, fcb, out, N);        // 9
}

// round 16
// speedup vs baseline: 1.4712x; 1.4712x over previous
#include <cuda_runtime.h>
#include <math.h>

#define NMAX 50000
#define EMAX 800000
#define SB   512     // scan block size

typedef unsigned long long ull;

// ---------------- scratch (device globals; no allocation allowed) ------------
__device__ float d_h1[NMAX * 256];   // layer1 transformed features
__device__ float d_al1[NMAX * 4];
__device__ float d_ar1[NMAX * 4];
__device__ float d_g1[NMAX];
__device__ float d_x2[NMAX * 256];   // elu(normalized aggregate) = GEMM2 input
__device__ float d_h2[NMAX * 64];
__device__ float d_al2[NMAX];
__device__ float d_ar2[NMAX];
__device__ float d_g2[NMAX];
// CSR (edges sorted by destination)
__device__ int   d_deg[NMAX];
__device__ int   d_cur[NMAX];
__device__ int   d_rs[NMAX + 1];
__device__ int   d_bt[(NMAX + SB - 1) / SB];
__device__ int   d_srcs[EMAX];

__device__ __forceinline__ float elu_f(float v) {
    return v > 0.f ? v : (__expf(v) - 1.0f);
}

// packed fp32x2 FMA (sm_103a FFMA2 — only reachable via PTX)
__device__ __forceinline__ ull ffma2(ull a, ull b, ull c) {
    ull d;
    asm("fma.rn.f32x2 %0, %1, %2, %3;" : "=l"(d) : "l"(a), "l"(b), "l"(c));
    return d;
}
__device__ __forceinline__ ull pk2(float v) {
    ull d;
    asm("mov.b64 %0, {%1, %2};" : "=l"(d) : "f"(v), "f"(v));
    return d;
}

// ---------------- fp32x2 packed SGEMM, double-buffered (round-13 proven) ------
// C[N,M] = A[N,K] @ B[K,M]; 128x64 block tile, BK=16, 256 threads, 8x4 microtile.
// rowbase: row offset for split-pipeline launches (row0 = rowbase + by*128).
template <int HS>
__global__ __launch_bounds__(256) void sgemm128(
        const float* __restrict__ A, const float* __restrict__ B,
        float* __restrict__ C, int rowbase, int N, int K, int M,
        const float* __restrict__ attl, const float* __restrict__ attr,
        float* __restrict__ alout, float* __restrict__ arout) {
    __shared__ float As[2][16][132];   // [buf][k][row]
    __shared__ float Bs[2][16][64];
    int tid = threadIdx.x;
    int tx = tid & 15, ty = tid >> 4;
    int row0 = rowbase + blockIdx.y * 128, col0 = blockIdx.x * 64;
    const int br = tid >> 4, bc = (tid & 15) * 4;

    ull acc[4][4];
    #pragma unroll
    for (int p = 0; p < 4; p++)
        #pragma unroll
        for (int j = 0; j < 4; j++)
            acc[p][j] = 0ull;

    float4 aR[2], bR;
    #pragma unroll
    for (int i = 0; i < 2; i++) {
        int f = tid + i * 256;
        int r = f >> 2, c = (f & 3) * 4;
        int row = row0 + r;
        aR[i] = make_float4(0.f, 0.f, 0.f, 0.f);
        if (row < N) aR[i] = *(const float4*)&A[(size_t)row * K + c];
    }
    bR = *(const float4*)&B[(size_t)br * M + col0 + bc];
    #pragma unroll
    for (int i = 0; i < 2; i++) {
        int f = tid + i * 256;
        int r = f >> 2, c = (f & 3) * 4;
        As[0][c + 0][r] = aR[i].x;
        As[0][c + 1][r] = aR[i].y;
        As[0][c + 2][r] = aR[i].z;
        As[0][c + 3][r] = aR[i].w;
    }
    *(float4*)&Bs[0][br][bc] = bR;
    __syncthreads();

    int nt = K >> 4;
    for (int t = 0; t < nt; t++) {
        int buf = t & 1;
        if (t + 1 < nt) {
            int k0 = (t + 1) << 4;
            #pragma unroll
            for (int i = 0; i < 2; i++) {
                int f = tid + i * 256;
                int r = f >> 2, c = (f & 3) * 4;
                int row = row0 + r;
                aR[i] = make_float4(0.f, 0.f, 0.f, 0.f);
                if (row < N) aR[i] = *(const float4*)&A[(size_t)row * K + k0 + c];
            }
            bR = *(const float4*)&B[(size_t)(k0 + br) * M + col0 + bc];
        }
        #pragma unroll
        for (int k = 0; k < 16; k++) {
            ull a[4];
            #pragma unroll
            for (int p = 0; p < 4; p++)
                a[p] = *(const ull*)&As[buf][k][ty * 8 + p * 2];
            float4 bv = *(const float4*)&Bs[buf][k][tx * 4];
            ull bj[4];
            bj[0] = pk2(bv.x); bj[1] = pk2(bv.y);
            bj[2] = pk2(bv.z); bj[3] = pk2(bv.w);
            #pragma unroll
            for (int p = 0; p < 4; p++)
                #pragma unroll
                for (int j = 0; j < 4; j++)
                    acc[p][j] = ffma2(a[p], bj[j], acc[p][j]);
        }
        if (t + 1 < nt) {
            int nb2 = buf ^ 1;
            #pragma unroll
            for (int i = 0; i < 2; i++) {
                int f = tid + i * 256;
                int r = f >> 2, c = (f & 3) * 4;
                As[nb2][c + 0][r] = aR[i].x;
                As[nb2][c + 1][r] = aR[i].y;
                As[nb2][c + 2][r] = aR[i].z;
                As[nb2][c + 3][r] = aR[i].w;
            }
            *(float4*)&Bs[nb2][br][bc] = bR;
            __syncthreads();
        }
    }
    float accf[8][4];
    #pragma unroll
    for (int p = 0; p < 4; p++)
        #pragma unroll
        for (int j = 0; j < 4; j++) {
            float2 f = *(float2*)&acc[p][j];
            accf[p * 2 + 0][j] = f.x;
            accf[p * 2 + 1][j] = f.y;
        }
    #pragma unroll
    for (int i = 0; i < 8; i++) {
        int row = row0 + ty * 8 + i;
        if (row < N)
            *(float4*)&C[(size_t)row * M + col0 + tx * 4] =
                make_float4(accf[i][0], accf[i][1], accf[i][2], accf[i][3]);
    }
    // fused attention-dot epilogue
    float lv[4], rv[4];
    #pragma unroll
    for (int j = 0; j < 4; j++) {
        lv[j] = attl[col0 + tx * 4 + j];
        rv[j] = attr[col0 + tx * 4 + j];
    }
    float pal[8], par[8];
    #pragma unroll
    for (int i = 0; i < 8; i++) {
        float sl = 0.f, sr = 0.f;
        #pragma unroll
        for (int j = 0; j < 4; j++) {
            sl += accf[i][j] * lv[j];
            sr += accf[i][j] * rv[j];
        }
        pal[i] = sl; par[i] = sr;
    }
    #pragma unroll
    for (int off = 1; off < 16; off <<= 1) {
        #pragma unroll
        for (int i = 0; i < 8; i++) {
            pal[i] += __shfl_xor_sync(0xffffffffu, pal[i], off);
            par[i] += __shfl_xor_sync(0xffffffffu, par[i], off);
        }
    }
    if (tx == 0) {
        int h = col0 >> 6;
        #pragma unroll
        for (int i = 0; i < 8; i++) {
            int row = row0 + ty * 8 + i;
            if (row < N) {
                alout[row * HS + h] = pal[i];
                arout[row * HS + h] = par[i];
            }
        }
    }
}

// ---------------- CSR build ---------------------------------------------------
__global__ void k_count(const int* __restrict__ dst, int E) {
    int e = blockIdx.x * blockDim.x + threadIdx.x;
    if (e < E) atomicAdd(&d_deg[dst[e]], 1);
}
__global__ void k_scan1(const float* __restrict__ x, int N) {
    __shared__ int sm[SB];
    int i = blockIdx.x * SB + threadIdx.x;
    int v = (i < N) ? d_deg[i] : 0;
    sm[threadIdx.x] = v;
    if (i < N)
        d_g1[i] = -0.1f * logf(fabsf(x[(size_t)i * 128 + 127]) + 1e-6f);
    __syncthreads();
    #pragma unroll
    for (int off = 1; off < SB; off <<= 1) {
        int t = (threadIdx.x >= off) ? sm[threadIdx.x - off] : 0;
        __syncthreads();
        sm[threadIdx.x] += t;
        __syncthreads();
    }
    if (i < N) d_rs[i] = sm[threadIdx.x] - v;
    if (threadIdx.x == SB - 1) d_bt[blockIdx.x] = sm[SB - 1];
}
__global__ void k_scan23(int N, int E) {
    __shared__ int soff;
    if (threadIdx.x == 0) soff = 0;
    __syncthreads();
    int v = (threadIdx.x < blockIdx.x) ? d_bt[threadIdx.x] : 0;
    #pragma unroll
    for (int off = 16; off; off >>= 1)
        v += __shfl_xor_sync(0xffffffffu, v, off);
    if ((threadIdx.x & 31) == 0 && v) atomicAdd(&soff, v);
    __syncthreads();
    int i = blockIdx.x * SB + threadIdx.x;
    if (i < N) d_rs[i] += soff;
    if (i == 0) d_rs[N] = E;
}
__global__ void k_scatter(const int* __restrict__ src, const int* __restrict__ dst, int E) {
    int e = blockIdx.x * blockDim.x + threadIdx.x;
    if (e >= E) return;
    int d = dst[e];
    int pos = d_rs[d] + atomicAdd(&d_cur[d], 1);
    d_srcs[pos] = src[e];
}

// ---------------- layer1 CSR aggregation: warp per dst node, node range -------
__global__ void agg1_csr(int base, int cnt) {
    int w = (blockIdx.x * blockDim.x + threadIdx.x) >> 5;
    int lane = threadIdx.x & 31;
    if (w >= cnt) return;
    int n = base + w;
    int beg = d_rs[n], end = d_rs[n + 1];
    float alh = (lane < 4) ? d_al1[n * 4 + lane] : 0.f;
    float4 accA = make_float4(0.f, 0.f, 0.f, 0.f);
    float4 accB = make_float4(0.f, 0.f, 0.f, 0.f);
    float wsum = 0.f;
    for (int p = beg; p < end; p++) {
        int s = d_srcs[p];
        float ex = 0.f;
        if (lane < 4) {
            float v = alh + d_ar1[s * 4 + lane];
            v = v > 0.f ? v : 0.01f * v;        // leaky relu
            v += d_g1[s];                       // guidance (shift-safe softmax)
            ex = __expf(v);
            wsum += ex;
        }
        float w0 = __shfl_sync(0xffffffffu, ex, 0);
        float w1 = __shfl_sync(0xffffffffu, ex, 1);
        float w2 = __shfl_sync(0xffffffffu, ex, 2);
        float w3 = __shfl_sync(0xffffffffu, ex, 3);
        float wa = (lane < 16) ? w0 : w1;
        float wb = (lane < 16) ? w2 : w3;
        const float4* hs = (const float4*)&d_h1[(size_t)s * 256];
        float4 a = hs[lane];
        float4 b = hs[lane + 32];
        accA.x += a.x * wa; accA.y += a.y * wa; accA.z += a.z * wa; accA.w += a.w * wa;
        accB.x += b.x * wb; accB.y += b.y * wb; accB.z += b.z * wb; accB.w += b.w * wb;
    }
    float s0 = __shfl_sync(0xffffffffu, wsum, 0);
    float s1 = __shfl_sync(0xffffffffu, wsum, 1);
    float s2 = __shfl_sync(0xffffffffu, wsum, 2);
    float s3 = __shfl_sync(0xffffffffu, wsum, 3);
    float inva = 1.f / (((lane < 16) ? s0 : s1) + 1e-16f);
    float invb = 1.f / (((lane < 16) ? s2 : s3) + 1e-16f);
    accA.x = elu_f(accA.x * inva); accA.y = elu_f(accA.y * inva);
    accA.z = elu_f(accA.z * inva); accA.w = elu_f(accA.w * inva);
    accB.x = elu_f(accB.x * invb); accB.y = elu_f(accB.y * invb);
    accB.z = elu_f(accB.z * invb); accB.w = elu_f(accB.w * invb);
    float* xr = &d_x2[(size_t)n * 256];
    *(float4*)&xr[lane * 4] = accA;
    *(float4*)&xr[128 + lane * 4] = accB;
    if (lane == 31)
        d_g2[n] = -0.1f * logf(fabsf(accB.w) + 1e-6f);
}

// ---------------- layer2 CSR aggregation + normalize + ELU + final FC ---------
__global__ void agg2_csr(const float* __restrict__ fcw, const float* __restrict__ fcb,
                         float* __restrict__ out, int N) {
    int n = (blockIdx.x * blockDim.x + threadIdx.x) >> 5;
    int lane = threadIdx.x & 31;
    if (n >= N) return;
    int beg = d_rs[n], end = d_rs[n + 1];
    float aln = d_al2[n];
    float2 acc = make_float2(0.f, 0.f);
    float wsum = 0.f;
    for (int p = beg; p < end; p++) {
        int s = d_srcs[p];
        float ex = 0.f;
        if (lane == 0) {
            float v = aln + d_ar2[s];
            v = v > 0.f ? v : 0.01f * v;
            v += d_g2[s];
            ex = __expf(v);
            wsum += ex;
        }
        ex = __shfl_sync(0xffffffffu, ex, 0);
        float2 hv = ((const float2*)&d_h2[(size_t)s * 64])[lane];
        acc.x += hv.x * ex;
        acc.y += hv.y * ex;
    }
    wsum = __shfl_sync(0xffffffffu, wsum, 0);
    float inv = 1.f / (wsum + 1e-16f);
    float v0 = elu_f(acc.x * inv);
    float v1 = elu_f(acc.y * inv);
    float dot = v0 * fcw[2 * lane] + v1 * fcw[2 * lane + 1];
    #pragma unroll
    for (int off = 16; off; off >>= 1)
        dot += __shfl_xor_sync(0xffffffffu, dot, off);
    if (lane == 0) out[n] = dot + fcb[0];
}

// ---------------- host launcher ----------------------------------------------
extern "C" void kernel_launch(void* const* d_in, const int* in_sizes, int n_in,
                              void* d_out, int out_size) {
    const float* x     = (const float*)d_in[0];
    const int*   ei    = (const int*)d_in[1];
    const float* W1    = (const float*)d_in[2];
    const float* attl1 = (const float*)d_in[3];
    const float* attr1 = (const float*)d_in[4];
    const float* W2    = (const float*)d_in[5];
    const float* attl2 = (const float*)d_in[6];
    const float* attr2 = (const float*)d_in[7];
    const float* fcw   = (const float*)d_in[8];
    const float* fcb   = (const float*)d_in[9];
    float* out = (float*)d_out;

    int N = in_sizes[0] / 128;
    int E = in_sizes[1] / 2;
    const int* src = ei;
    const int* dst = ei + E;

    void *ph1, *ph2, *px2, *pdeg, *pcur;
    void *pal1, *par1, *pal2, *par2;
    cudaGetSymbolAddress(&ph1, d_h1);
    cudaGetSymbolAddress(&ph2, d_h2);
    cudaGetSymbolAddress(&px2, d_x2);
    cudaGetSymbolAddress(&pdeg, d_deg);
    cudaGetSymbolAddress(&pcur, d_cur);
    cudaGetSymbolAddress(&pal1, d_al1);
    cudaGetSymbolAddress(&par1, d_ar1);
    cudaGetSymbolAddress(&pal2, d_al2);
    cudaGetSymbolAddress(&par2, d_ar2);

    // one-time setup (first call is the uncaptured correctness run)
    static cudaStream_t s2 = nullptr;
    static cudaEvent_t evFork = nullptr, evJoin = nullptr, evA = nullptr, evB = nullptr;
    if (!s2) {
        cudaStreamCreateWithFlags(&s2, cudaStreamNonBlocking);
        cudaEventCreateWithFlags(&evFork, cudaEventDisableTiming);
        cudaEventCreateWithFlags(&evJoin, cudaEventDisableTiming);
        cudaEventCreateWithFlags(&evA, cudaEventDisableTiming);
        cudaEventCreateWithFlags(&evB, cudaEventDisableTiming);
    }

    const int TB = 256;
    int gy = (N + 127) / 128;       // 128-row blocks
    int gy1 = gy / 2;               // first-half blocks
    int rows1 = gy1 * 128;          // node split point
    int gy2 = gy - gy1;
    int nb = (N + SB - 1) / SB;

    // ---- fork: CSR build on s2, GEMM1 on main stream, concurrently ----
    cudaEventRecord(evFork, 0);
    cudaStreamWaitEvent(s2, evFork, 0);

    cudaMemsetAsync(pdeg, 0, sizeof(int) * (size_t)N, s2);             // 0
    cudaMemsetAsync(pcur, 0, sizeof(int) * (size_t)N, s2);             // 1
    k_count<<<(E + TB - 1) / TB, TB, 0, s2>>>(dst, E);                 // 2
    k_scan1<<<nb, SB, 0, s2>>>(x, N);                                  // 3 (+g1)
    k_scan23<<<nb, SB, 0, s2>>>(N, E);                                 // 4

    sgemm128<4><<<dim3(4, gy), TB>>>(x, W1, (float*)ph1, 0, N, 128, 256, // 5 (main)
                                     attl1, attr1, (float*)pal1, (float*)par1);

    k_scatter<<<(E + TB - 1) / TB, TB, 0, s2>>>(src, dst, E);          // 6
    cudaEventRecord(evJoin, s2);

    // ---- join, then split-pipeline agg1 ∥ GEMM2 ----
    cudaStreamWaitEvent(0, evJoin, 0);
    agg1_csr<<<(rows1 * 32 + TB - 1) / TB, TB>>>(0, rows1);            // agg1 first half
    cudaEventRecord(evA, 0);
    cudaStreamWaitEvent(s2, evA, 0);
    agg1_csr<<<((N - rows1) * 32 + TB - 1) / TB, TB, 0, s2>>>(rows1, N - rows1); // second half on s2
    cudaEventRecord(evB, s2);

    sgemm128<1><<<dim3(1, gy1), TB>>>((const float*)px2, W2, (float*)ph2, // GEMM2 first half ∥ agg1b
                                      0, N, 256, 64, attl2, attr2,
                                      (float*)pal2, (float*)par2);
    cudaStreamWaitEvent(0, evB, 0);
    sgemm128<1><<<dim3(1, gy2), TB>>>((const float*)px2, W2, (float*)ph2, // GEMM2 second half
                                      rows1, N, 256, 64, attl2, attr2,
                                      (float*)pal2, (float*)par2);
    agg2_csr<<<(N * 32 + TB - 1) / TB, TB>>>(fcw, fcb, out, N);
}

// round 17
// speedup vs baseline: 1.5581x; 1.0591x over previous
#include <cuda_runtime.h>
#include <math.h>

#define NMAX 50000
#define EMAX 800000
#define SB   512     // scan block size

typedef unsigned long long ull;

// ---------------- scratch (device globals; no allocation allowed) ------------
__device__ float d_h1[NMAX * 256];   // layer1 transformed features
__device__ float d_al1[NMAX * 4];    // dst-side attention dots (layer1)
__device__ float d_att1[NMAX * 8];   // src-side packed: {ar1[4], g1, pad[3]} per node
__device__ float d_x2[NMAX * 256];   // elu(normalized aggregate) = GEMM2 input
__device__ float d_h2[NMAX * 64];
__device__ float d_al2[NMAX];        // dst-side attention dot (layer2)
__device__ float d_att2[NMAX * 2];   // src-side packed: {ar2, g2} per node
// CSR (edges sorted by destination)
__device__ int   d_deg[NMAX];
__device__ int   d_cur[NMAX];
__device__ int   d_rs[NMAX + 1];
__device__ int   d_bt[(NMAX + SB - 1) / SB];
__device__ int   d_srcs[EMAX];

__device__ __forceinline__ float elu_f(float v) {
    return v > 0.f ? v : (__expf(v) - 1.0f);
}

// packed fp32x2 FMA (sm_103a FFMA2 — only reachable via PTX)
__device__ __forceinline__ ull ffma2(ull a, ull b, ull c) {
    ull d;
    asm("fma.rn.f32x2 %0, %1, %2, %3;" : "=l"(d) : "l"(a), "l"(b), "l"(c));
    return d;
}
__device__ __forceinline__ ull pk2(float v) {
    ull d;
    asm("mov.b64 %0, {%1, %2};" : "=l"(d) : "f"(v), "f"(v));
    return d;
}

// ---------------- fp32x2 packed SGEMM, double-buffered (round-13 proven) ------
// C[N,M] = A[N,K] @ B[K,M]; 128x64 block tile, BK=16, 256 threads, 8x4 microtile.
// ALS/ARS: strides for attention-dot outputs (alout[row*ALS+h], arout[row*ARS+h]).
template <int ALS, int ARS>
__global__ __launch_bounds__(256) void sgemm128(
        const float* __restrict__ A, const float* __restrict__ B,
        float* __restrict__ C, int N, int K, int M,
        const float* __restrict__ attl, const float* __restrict__ attr,
        float* __restrict__ alout, float* __restrict__ arout) {
    __shared__ float As[2][16][132];   // [buf][k][row]
    __shared__ float Bs[2][16][64];
    int tid = threadIdx.x;
    int tx = tid & 15, ty = tid >> 4;
    int row0 = blockIdx.y * 128, col0 = blockIdx.x * 64;
    const int br = tid >> 4, bc = (tid & 15) * 4;

    ull acc[4][4];
    #pragma unroll
    for (int p = 0; p < 4; p++)
        #pragma unroll
        for (int j = 0; j < 4; j++)
            acc[p][j] = 0ull;

    float4 aR[2], bR;
    #pragma unroll
    for (int i = 0; i < 2; i++) {
        int f = tid + i * 256;
        int r = f >> 2, c = (f & 3) * 4;
        int row = row0 + r;
        aR[i] = make_float4(0.f, 0.f, 0.f, 0.f);
        if (row < N) aR[i] = *(const float4*)&A[(size_t)row * K + c];
    }
    bR = *(const float4*)&B[(size_t)br * M + col0 + bc];
    #pragma unroll
    for (int i = 0; i < 2; i++) {
        int f = tid + i * 256;
        int r = f >> 2, c = (f & 3) * 4;
        As[0][c + 0][r] = aR[i].x;
        As[0][c + 1][r] = aR[i].y;
        As[0][c + 2][r] = aR[i].z;
        As[0][c + 3][r] = aR[i].w;
    }
    *(float4*)&Bs[0][br][bc] = bR;
    __syncthreads();

    int nt = K >> 4;
    for (int t = 0; t < nt; t++) {
        int buf = t & 1;
        if (t + 1 < nt) {
            int k0 = (t + 1) << 4;
            #pragma unroll
            for (int i = 0; i < 2; i++) {
                int f = tid + i * 256;
                int r = f >> 2, c = (f & 3) * 4;
                int row = row0 + r;
                aR[i] = make_float4(0.f, 0.f, 0.f, 0.f);
                if (row < N) aR[i] = *(const float4*)&A[(size_t)row * K + k0 + c];
            }
            bR = *(const float4*)&B[(size_t)(k0 + br) * M + col0 + bc];
        }
        #pragma unroll
        for (int k = 0; k < 16; k++) {
            ull a[4];
            #pragma unroll
            for (int p = 0; p < 4; p++)
                a[p] = *(const ull*)&As[buf][k][ty * 8 + p * 2];
            float4 bv = *(const float4*)&Bs[buf][k][tx * 4];
            ull bj[4];
            bj[0] = pk2(bv.x); bj[1] = pk2(bv.y);
            bj[2] = pk2(bv.z); bj[3] = pk2(bv.w);
            #pragma unroll
            for (int p = 0; p < 4; p++)
                #pragma unroll
                for (int j = 0; j < 4; j++)
                    acc[p][j] = ffma2(a[p], bj[j], acc[p][j]);
        }
        if (t + 1 < nt) {
            int nb2 = buf ^ 1;
            #pragma unroll
            for (int i = 0; i < 2; i++) {
                int f = tid + i * 256;
                int r = f >> 2, c = (f & 3) * 4;
                As[nb2][c + 0][r] = aR[i].x;
                As[nb2][c + 1][r] = aR[i].y;
                As[nb2][c + 2][r] = aR[i].z;
                As[nb2][c + 3][r] = aR[i].w;
            }
            *(float4*)&Bs[nb2][br][bc] = bR;
            __syncthreads();
        }
    }
    float accf[8][4];
    #pragma unroll
    for (int p = 0; p < 4; p++)
        #pragma unroll
        for (int j = 0; j < 4; j++) {
            float2 f = *(float2*)&acc[p][j];
            accf[p * 2 + 0][j] = f.x;
            accf[p * 2 + 1][j] = f.y;
        }
    #pragma unroll
    for (int i = 0; i < 8; i++) {
        int row = row0 + ty * 8 + i;
        if (row < N)
            *(float4*)&C[(size_t)row * M + col0 + tx * 4] =
                make_float4(accf[i][0], accf[i][1], accf[i][2], accf[i][3]);
    }
    // fused attention-dot epilogue (64-col tile == one head)
    float lv[4], rv[4];
    #pragma unroll
    for (int j = 0; j < 4; j++) {
        lv[j] = attl[col0 + tx * 4 + j];
        rv[j] = attr[col0 + tx * 4 + j];
    }
    float pal[8], par[8];
    #pragma unroll
    for (int i = 0; i < 8; i++) {
        float sl = 0.f, sr = 0.f;
        #pragma unroll
        for (int j = 0; j < 4; j++) {
            sl += accf[i][j] * lv[j];
            sr += accf[i][j] * rv[j];
        }
        pal[i] = sl; par[i] = sr;
    }
    #pragma unroll
    for (int off = 1; off < 16; off <<= 1) {
        #pragma unroll
        for (int i = 0; i < 8; i++) {
            pal[i] += __shfl_xor_sync(0xffffffffu, pal[i], off);
            par[i] += __shfl_xor_sync(0xffffffffu, par[i], off);
        }
    }
    if (tx == 0) {
        int h = col0 >> 6;
        #pragma unroll
        for (int i = 0; i < 8; i++) {
            int row = row0 + ty * 8 + i;
            if (row < N) {
                alout[row * ALS + h] = pal[i];
                arout[row * ARS + h] = par[i];
            }
        }
    }
}

// ---------------- CSR build ---------------------------------------------------
__global__ void k_count(const int* __restrict__ dst, int E) {
    int e = blockIdx.x * blockDim.x + threadIdx.x;
    if (e < E) atomicAdd(&d_deg[dst[e]], 1);
}
// scan1 + layer1 guidance fused (g1 goes into packed att1 slot 4)
__global__ void k_scan1(const float* __restrict__ x, int N) {
    __shared__ int sm[SB];
    int i = blockIdx.x * SB + threadIdx.x;
    int v = (i < N) ? d_deg[i] : 0;
    sm[threadIdx.x] = v;
    if (i < N)
        d_att1[i * 8 + 4] = -0.1f * logf(fabsf(x[(size_t)i * 128 + 127]) + 1e-6f);
    __syncthreads();
    #pragma unroll
    for (int off = 1; off < SB; off <<= 1) {
        int t = (threadIdx.x >= off) ? sm[threadIdx.x - off] : 0;
        __syncthreads();
        sm[threadIdx.x] += t;
        __syncthreads();
    }
    if (i < N) d_rs[i] = sm[threadIdx.x] - v;
    if (threadIdx.x == SB - 1) d_bt[blockIdx.x] = sm[SB - 1];
}
__global__ void k_scan23(int N, int E) {
    __shared__ int soff;
    if (threadIdx.x == 0) soff = 0;
    __syncthreads();
    int v = (threadIdx.x < blockIdx.x) ? d_bt[threadIdx.x] : 0;
    #pragma unroll
    for (int off = 16; off; off >>= 1)
        v += __shfl_xor_sync(0xffffffffu, v, off);
    if ((threadIdx.x & 31) == 0 && v) atomicAdd(&soff, v);
    __syncthreads();
    int i = blockIdx.x * SB + threadIdx.x;
    if (i < N) d_rs[i] += soff;
    if (i == 0) d_rs[N] = E;
}
__global__ void k_scatter(const int* __restrict__ src, const int* __restrict__ dst, int E) {
    int e = blockIdx.x * blockDim.x + threadIdx.x;
    if (e >= E) return;
    int d = dst[e];
    int pos = d_rs[d] + atomicAdd(&d_cur[d], 1);
    d_srcs[pos] = src[e];
}

// ---------------- layer1 CSR aggregation: warp per dst node -------------------
// Src-side attention data packed in one 32B slot -> ONE random sector per edge
// (vs two before: ar1 sector + g1 sector).
__global__ void agg1_csr(int N) {
    int n = (blockIdx.x * blockDim.x + threadIdx.x) >> 5;
    int lane = threadIdx.x & 31;
    if (n >= N) return;
    int beg = d_rs[n], end = d_rs[n + 1];
    float alh = (lane < 4) ? d_al1[n * 4 + lane] : 0.f;
    float4 accA = make_float4(0.f, 0.f, 0.f, 0.f);
    float4 accB = make_float4(0.f, 0.f, 0.f, 0.f);
    float wsum = 0.f;
    for (int p = beg; p < end; p++) {
        int s = d_srcs[p];
        float ex = 0.f;
        if (lane < 4) {
            float ar = d_att1[s * 8 + lane];
            float g  = d_att1[s * 8 + 4];      // same 32B sector as ar
            float v = alh + ar;
            v = v > 0.f ? v : 0.01f * v;        // leaky relu
            v += g;                             // guidance (shift-safe softmax)
            ex = __expf(v);
            wsum += ex;
        }
        float w0 = __shfl_sync(0xffffffffu, ex, 0);
        float w1 = __shfl_sync(0xffffffffu, ex, 1);
        float w2 = __shfl_sync(0xffffffffu, ex, 2);
        float w3 = __shfl_sync(0xffffffffu, ex, 3);
        float wa = (lane < 16) ? w0 : w1;
        float wb = (lane < 16) ? w2 : w3;
        const float4* hs = (const float4*)&d_h1[(size_t)s * 256];
        float4 a = hs[lane];
        float4 b = hs[lane + 32];
        accA.x += a.x * wa; accA.y += a.y * wa; accA.z += a.z * wa; accA.w += a.w * wa;
        accB.x += b.x * wb; accB.y += b.y * wb; accB.z += b.z * wb; accB.w += b.w * wb;
    }
    float s0 = __shfl_sync(0xffffffffu, wsum, 0);
    float s1 = __shfl_sync(0xffffffffu, wsum, 1);
    float s2 = __shfl_sync(0xffffffffu, wsum, 2);
    float s3 = __shfl_sync(0xffffffffu, wsum, 3);
    float inva = 1.f / (((lane < 16) ? s0 : s1) + 1e-16f);
    float invb = 1.f / (((lane < 16) ? s2 : s3) + 1e-16f);
    accA.x = elu_f(accA.x * inva); accA.y = elu_f(accA.y * inva);
    accA.z = elu_f(accA.z * inva); accA.w = elu_f(accA.w * inva);
    accB.x = elu_f(accB.x * invb); accB.y = elu_f(accB.y * invb);
    accB.z = elu_f(accB.z * invb); accB.w = elu_f(accB.w * invb);
    float* xr = &d_x2[(size_t)n * 256];
    *(float4*)&xr[lane * 4] = accA;
    *(float4*)&xr[128 + lane * 4] = accB;
    if (lane == 31)   // layer2 guidance -> packed att2 slot 1
        d_att2[n * 2 + 1] = -0.1f * logf(fabsf(accB.w) + 1e-6f);
}

// ---------------- layer2 CSR aggregation + normalize + ELU + final FC ---------
__global__ void agg2_csr(const float* __restrict__ fcw, const float* __restrict__ fcb,
                         float* __restrict__ out, int N) {
    int n = (blockIdx.x * blockDim.x + threadIdx.x) >> 5;
    int lane = threadIdx.x & 31;
    if (n >= N) return;
    int beg = d_rs[n], end = d_rs[n + 1];
    float aln = d_al2[n];
    float2 acc = make_float2(0.f, 0.f);
    float wsum = 0.f;
    for (int p = beg; p < end; p++) {
        int s = d_srcs[p];
        float ex = 0.f;
        if (lane == 0) {
            float2 ag = *(const float2*)&d_att2[s * 2];   // {ar2, g2} one LDG.64
            float v = aln + ag.x;
            v = v > 0.f ? v : 0.01f * v;
            v += ag.y;
            ex = __expf(v);
            wsum += ex;
        }
        ex = __shfl_sync(0xffffffffu, ex, 0);
        float2 hv = ((const float2*)&d_h2[(size_t)s * 64])[lane];
        acc.x += hv.x * ex;
        acc.y += hv.y * ex;
    }
    wsum = __shfl_sync(0xffffffffu, wsum, 0);
    float inv = 1.f / (wsum + 1e-16f);
    float v0 = elu_f(acc.x * inv);
    float v1 = elu_f(acc.y * inv);
    float dot = v0 * fcw[2 * lane] + v1 * fcw[2 * lane + 1];
    #pragma unroll
    for (int off = 16; off; off >>= 1)
        dot += __shfl_xor_sync(0xffffffffu, dot, off);
    if (lane == 0) out[n] = dot + fcb[0];
}

// ---------------- host launcher ----------------------------------------------
extern "C" void kernel_launch(void* const* d_in, const int* in_sizes, int n_in,
                              void* d_out, int out_size) {
    const float* x     = (const float*)d_in[0];
    const int*   ei    = (const int*)d_in[1];
    const float* W1    = (const float*)d_in[2];
    const float* attl1 = (const float*)d_in[3];
    const float* attr1 = (const float*)d_in[4];
    const float* W2    = (const float*)d_in[5];
    const float* attl2 = (const float*)d_in[6];
    const float* attr2 = (const float*)d_in[7];
    const float* fcw   = (const float*)d_in[8];
    const float* fcb   = (const float*)d_in[9];
    float* out = (float*)d_out;

    int N = in_sizes[0] / 128;
    int E = in_sizes[1] / 2;
    const int* src = ei;
    const int* dst = ei + E;

    void *ph1, *ph2, *px2, *pdeg, *pcur;
    void *pal1, *patt1, *pal2, *patt2;
    cudaGetSymbolAddress(&ph1, d_h1);
    cudaGetSymbolAddress(&ph2, d_h2);
    cudaGetSymbolAddress(&px2, d_x2);
    cudaGetSymbolAddress(&pdeg, d_deg);
    cudaGetSymbolAddress(&pcur, d_cur);
    cudaGetSymbolAddress(&pal1, d_al1);
    cudaGetSymbolAddress(&patt1, d_att1);
    cudaGetSymbolAddress(&pal2, d_al2);
    cudaGetSymbolAddress(&patt2, d_att2);

    // one-time setup (first call is the uncaptured correctness run)
    static cudaStream_t s2 = nullptr;
    static cudaEvent_t evFork = nullptr, evJoin = nullptr;
    if (!s2) {
        cudaStreamCreateWithFlags(&s2, cudaStreamNonBlocking);
        cudaEventCreateWithFlags(&evFork, cudaEventDisableTiming);
        cudaEventCreateWithFlags(&evJoin, cudaEventDisableTiming);
    }

    const int TB = 256;
    int gy = (N + 127) / 128;
    int nb = (N + SB - 1) / SB;

    // ---- fork: CSR build on s2, GEMM1 on main stream, concurrently ----
    cudaEventRecord(evFork, 0);
    cudaStreamWaitEvent(s2, evFork, 0);

    cudaMemsetAsync(pdeg, 0, sizeof(int) * (size_t)N, s2);             // 0
    cudaMemsetAsync(pcur, 0, sizeof(int) * (size_t)N, s2);             // 1
    k_count<<<(E + TB - 1) / TB, TB, 0, s2>>>(dst, E);                 // 2
    k_scan1<<<nb, SB, 0, s2>>>(x, N);                                  // 3 (+g1)
    k_scan23<<<nb, SB, 0, s2>>>(N, E);                                 // 4

    // GEMM1: al1 stride 4, ar -> packed att1 stride 8
    sgemm128<4, 8><<<dim3(4, gy), TB>>>(x, W1, (float*)ph1, N, 128, 256, // 5 (main)
                                        attl1, attr1,
                                        (float*)pal1, (float*)patt1);

    k_scatter<<<(E + TB - 1) / TB, TB, 0, s2>>>(src, dst, E);          // 6
    cudaEventRecord(evJoin, s2);

    // ---- join: rest of the pipeline on the main stream ----
    cudaStreamWaitEvent(0, evJoin, 0);
    agg1_csr<<<(N * 32 + TB - 1) / TB, TB>>>(N);                       // 7
    // GEMM2: al2 stride 1, ar -> packed att2 stride 2
    sgemm128<1, 2><<<dim3(1, gy), TB>>>((const float*)px2, W2,         // 8
                                        (float*)ph2, N, 256, 64,
                                        attl2, attr2,
                                        (float*)pal2, (float*)patt2);
    agg2_csr<<<(N * 32 + TB - 1) / TB, TB>>>(fcw, fcb, out, N);        // 9
}